// round 14
// baseline (speedup 1.0000x reference)
#include <cuda_runtime.h>
#include <cuda_bf16.h>
#include <cstdint>

typedef __nv_bfloat16 bf16;

static constexpr int cB = 16;
static constexpr int cS = 512;
static constexpr int cIN = 32;
static constexpr int cD = 768;
static constexpr int cH = 12;
static constexpr int cDH = 64;
static constexpr int cL = 6;
static constexpr int cF = 3072;
static constexpr int cM = cB * cS;              // 8192 tokens
static constexpr float cEPS = 1e-5f;
static constexpr float cNEG = -1e9f;

// ---------------- scratch (device globals; no allocation) ----------------
__device__ __align__(256) float g_h[cM * cD];
__device__ __align__(256) float g_o[cM * cD];
__device__ __align__(256) float g_s[(size_t)cB * cH * cS * cS];
__device__ __align__(256) bf16 g_hh[cM * cD];
__device__ __align__(256) bf16 g_hl[cM * cD];
__device__ __align__(256) bf16 g_qh[cM * cD];
__device__ __align__(256) bf16 g_ql[cM * cD];
__device__ __align__(256) bf16 g_kh[cM * cD];
__device__ __align__(256) bf16 g_kl[cM * cD];
__device__ __align__(256) bf16 g_vth[cM * cD];
__device__ __align__(256) bf16 g_vtl[cM * cD];
__device__ __align__(256) bf16 g_ph[(size_t)cB * cH * cS * cS];
__device__ __align__(256) bf16 g_pl[(size_t)cB * cH * cS * cS];
__device__ __align__(256) bf16 g_fh[(size_t)cM * cF];
__device__ __align__(256) bf16 g_fl[(size_t)cM * cF];
__device__ __align__(256) bf16 g_wqh[cL * cD * cD];
__device__ __align__(256) bf16 g_wql[cL * cD * cD];
__device__ __align__(256) bf16 g_wkh[cL * cD * cD];
__device__ __align__(256) bf16 g_wkl[cL * cD * cD];
__device__ __align__(256) bf16 g_wvh[cL * cD * cD];
__device__ __align__(256) bf16 g_wvl[cL * cD * cD];
__device__ __align__(256) bf16 g_w1h[(size_t)cL * cD * cF];
__device__ __align__(256) bf16 g_w1l[(size_t)cL * cD * cF];
__device__ __align__(256) bf16 g_w2h[(size_t)cL * cF * cD];
__device__ __align__(256) bf16 g_w2l[(size_t)cL * cF * cD];

// ---------------- helpers ----------------
__device__ __forceinline__ uint32_t smem_to_u32(const void* smem_ptr) {
    uint32_t addr;
    asm("{ .reg .u64 tmp; cvta.to.shared.u64 tmp, %1; cvt.u32.u64 %0, tmp; }"
        : "=r"(addr) : "l"(smem_ptr));
    return addr;
}

#define LDSM_X4(r0, r1, r2, r3, addr) \
    asm volatile("ldmatrix.sync.aligned.m8n8.x4.shared.b16 {%0,%1,%2,%3}, [%4];" \
        : "=r"(r0), "=r"(r1), "=r"(r2), "=r"(r3) : "r"(addr))

#define MMA16816(d, a, b0, b1) \
    asm volatile("mma.sync.aligned.m16n8k16.row.col.f32.bf16.bf16.f32 " \
        "{%0,%1,%2,%3}, {%4,%5,%6,%7}, {%8,%9}, {%0,%1,%2,%3};" \
        : "+f"((d)[0]), "+f"((d)[1]), "+f"((d)[2]), "+f"((d)[3]) \
        : "r"((a)[0]), "r"((a)[1]), "r"((a)[2]), "r"((a)[3]), "r"(b0), "r"(b1))

__device__ __forceinline__ void bsplit(float v, bf16& hi, bf16& lo) {
    hi = __float2bfloat16(v);
    lo = __float2bfloat16(v - __bfloat162float(hi));
}

// ==========================================================================
// bf16x3 GEMM via mma.sync (HMMA):  C[M,N] = A[M,K] @ B[N,K]^T
// M tile 128 (grid.y), N tile NT (grid.x), K chunked by 64, batched grid.z.
// 8 warps: warpM = wid&3 (32 rows), warpN = wid>>2 (NT/2 cols).
// Smem tiles pitch-72 bf16 rows (144B): uint4-aligned, ldmatrix conflict-free.
// MODE: 0=fp32+bias  1=hi/lo+bias  2=V-transpose hi/lo+bias
//       3=scores (scale+mask, fp32)  4=PV (fp32 strided)  5=ReLU hi/lo+bias
// ==========================================================================
template<int NT, int MODE>
__global__ void __launch_bounds__(256, 2) gemm_tc(
    const bf16* __restrict__ Ah, const bf16* __restrict__ Al,
    const bf16* __restrict__ Bh, const bf16* __restrict__ Bl,
    const float* __restrict__ bias,
    float* __restrict__ outF, bf16* __restrict__ outH, bf16* __restrict__ outL,
    int K, int lda, int ldb, int ldOut,
    long long aS1, long long aS2, long long bS1, long long bS2,
    const int* __restrict__ lens)
{
    extern __shared__ char smem[];
    const uint32_t sb = smem_to_u32(smem);
    const int tid = threadIdx.x;
    const int wid = tid >> 5;
    const int lid = tid & 31;
    const int z = blockIdx.z;
    const int row0 = blockIdx.y * 128;
    const int col0 = blockIdx.x * NT;
    const size_t aOff = (size_t)(z / cH) * aS1 + (size_t)(z % cH) * aS2;
    const size_t bOff = (size_t)(z / cH) * bS1 + (size_t)(z % cH) * bS2;

    const int warpM = wid & 3;          // 0..3 -> 32 rows each
    const int warpN = wid >> 2;         // 0..1 -> NT/2 cols each
    constexpr int WN = NT / 2;
    constexpr int NTILES = NT / 16;     // n-tiles of 8 per warp

    constexpr uint32_t PITCH_E = 72;              // bf16 elems per tile row
    constexpr uint32_t OFF_AH = 0;
    constexpr uint32_t OFF_AL = 128 * PITCH_E * 2;            // 18432
    constexpr uint32_t OFF_BH = OFF_AL * 2;                    // 36864
    constexpr uint32_t OFF_BL = OFF_BH + (uint32_t)NT * PITCH_E * 2;

    float acc[2][NTILES][4];
    #pragma unroll
    for (int mt = 0; mt < 2; mt++)
        #pragma unroll
        for (int nt = 0; nt < NTILES; nt++)
            #pragma unroll
            for (int i = 0; i < 4; i++)
                acc[mt][nt][i] = 0.f;

    const int nch = K >> 6;
    for (int c = 0; c < nch; c++) {
        const int k0c = c << 6;
        #pragma unroll
        for (int v = tid; v < 1024; v += 256) {          // A tile: 128 x 64
            int r = v >> 3;
            int kc = (v & 7) << 3;
            size_t src = aOff + (size_t)(row0 + r) * lda + (size_t)(k0c + kc);
            uint32_t dst = (uint32_t)(r * PITCH_E + kc) * 2;
            *(uint4*)(smem + OFF_AH + dst) = *(const uint4*)(Ah + src);
            *(uint4*)(smem + OFF_AL + dst) = *(const uint4*)(Al + src);
        }
        #pragma unroll
        for (int v = tid; v < NT * 8; v += 256) {        // B tile: NT x 64
            int r = v >> 3;
            int kc = (v & 7) << 3;
            size_t src = bOff + (size_t)(col0 + r) * ldb + (size_t)(k0c + kc);
            uint32_t dst = (uint32_t)(r * PITCH_E + kc) * 2;
            *(uint4*)(smem + OFF_BH + dst) = *(const uint4*)(Bh + src);
            *(uint4*)(smem + OFF_BL + dst) = *(const uint4*)(Bl + src);
        }
        __syncthreads();

        #pragma unroll
        for (int p = 0; p < 3; p++) {    // hi*hi, hi*lo, lo*hi
            const uint32_t Ab = sb + (p == 2 ? OFF_AL : OFF_AH);
            const uint32_t Bb = sb + (p == 1 ? OFF_BL : OFF_BH);
            #pragma unroll
            for (int ks = 0; ks < 4; ks++) {
                const int kk = ks * 16;
                uint32_t afr[2][4];
                #pragma unroll
                for (int mt = 0; mt < 2; mt++) {
                    uint32_t addr = Ab +
                        ((uint32_t)(warpM * 32 + mt * 16 + (lid & 15)) * PITCH_E
                         + (uint32_t)(kk + (lid >> 4) * 8)) * 2;
                    LDSM_X4(afr[mt][0], afr[mt][1], afr[mt][2], afr[mt][3], addr);
                }
                #pragma unroll
                for (int nt = 0; nt < NTILES; nt += 2) {
                    uint32_t b0, b1, b2, b3;
                    uint32_t addr = Bb +
                        ((uint32_t)(warpN * WN + nt * 8 + ((lid >> 4) & 1) * 8 + (lid & 7)) * PITCH_E
                         + (uint32_t)(kk + ((lid >> 3) & 1) * 8)) * 2;
                    LDSM_X4(b0, b1, b2, b3, addr);
                    #pragma unroll
                    for (int mt = 0; mt < 2; mt++) {
                        MMA16816(acc[mt][nt],     afr[mt], b0, b1);
                        MMA16816(acc[mt][nt + 1], afr[mt], b2, b3);
                    }
                }
            }
        }
        __syncthreads();
    }

    // --- epilogue 1: registers -> smem f32, pitch NT+1 ---
    const int PITCH = NT + 1;
    float* sep = (float*)smem;
    #pragma unroll
    for (int mt = 0; mt < 2; mt++)
        #pragma unroll
        for (int nt = 0; nt < NTILES; nt++)
            #pragma unroll
            for (int i = 0; i < 4; i++) {
                int row = warpM * 32 + mt * 16 + (lid >> 2) + (i >> 1) * 8;
                int col = warpN * WN + nt * 8 + (lid & 3) * 2 + (i & 1);
                sep[row * PITCH + col] = acc[mt][nt][i];
            }
    __syncthreads();

    // --- epilogue 2: smem -> global, per-mode ---
    const int total = 128 * NT;
    for (int i = tid; i < total; i += 256) {
        if (MODE == 2) {
            int r = i & 127;
            int c2 = i >> 7;
            float v = sep[r * PITCH + c2] + bias[col0 + c2];
            int tokr = row0 + r;
            int gb = tokr >> 9;
            int gs = tokr & (cS - 1);
            int gc = col0 + c2;
            int h2 = gc >> 6;
            int dd = gc & 63;
            size_t o = (((size_t)(gb * cH + h2)) * cDH + dd) * cS + gs;
            bf16 hi, lo;
            bsplit(v, hi, lo);
            outH[o] = hi;
            outL[o] = lo;
        } else if (MODE == 4) {
            int c2 = i & 63;
            int r = i >> 6;
            float v = sep[r * PITCH + c2];
            int gb = z / cH;
            int h2 = z % cH;
            outF[((size_t)gb * cS + row0 + r) * cD + h2 * cDH + c2] = v;
        } else if (MODE == 3) {
            int c2 = i & (NT - 1);
            int r = i / NT;
            float v = sep[r * PITCH + c2];
            int len = lens[z / cH];
            v = (row0 + r < len && col0 + c2 < len) ? v * 0.125f : cNEG;
            outF[((size_t)z * cS + row0 + r) * cS + col0 + c2] = v;
        } else {
            int c2 = i & (NT - 1);
            int r = i / NT;
            float v = sep[r * PITCH + c2] + bias[col0 + c2];
            if (MODE == 5) v = fmaxf(v, 0.f);
            size_t o = (size_t)(row0 + r) * ldOut + (size_t)(col0 + c2);
            if (MODE == 0) {
                outF[o] = v;
            } else {
                bf16 hi, lo;
                bsplit(v, hi, lo);
                outH[o] = hi;
                outL[o] = lo;
            }
        }
    }
}

// ---------------- weight transpose + split: W[K,N] -> WT[N,K] hi/lo ----------------
__global__ void __launch_bounds__(256) transpose_split(
    const float* __restrict__ src, bf16* __restrict__ dh, bf16* __restrict__ dl,
    int K, int N)
{
    __shared__ float t[32][33];
    size_t base = (size_t)blockIdx.z * K * N;
    int k0 = blockIdx.x * 32;
    int n0 = blockIdx.y * 32;
    int tx = threadIdx.x & 31;
    int ty = threadIdx.x >> 5;
    #pragma unroll
    for (int i = 0; i < 32; i += 8) {
        t[ty + i][tx] = src[base + (size_t)(k0 + ty + i) * N + (n0 + tx)];
    }
    __syncthreads();
    #pragma unroll
    for (int i = 0; i < 32; i += 8) {
        float v = t[tx][ty + i];
        size_t o = base + (size_t)(n0 + ty + i) * K + (k0 + tx);
        bf16 hi, lo;
        bsplit(v, hi, lo);
        dh[o] = hi;
        dl[o] = lo;
    }
}

// ---------------- embed ----------------
__global__ void __launch_bounds__(256) embed_kernel(
    const float* __restrict__ x, const float* __restrict__ inw,
    const float* __restrict__ inb, const float* __restrict__ pos)
{
    int bs = blockIdx.x;
    int s = bs & (cS - 1);
    __shared__ float xs[cIN];
    int tid = threadIdx.x;
    if (tid < cIN) xs[tid] = x[(size_t)bs * cIN + tid];
    __syncthreads();
    #pragma unroll
    for (int i = 0; i < 3; i++) {
        int d = tid + i * 256;
        float a = inb[d] + pos[(size_t)s * cD + d];
        #pragma unroll
        for (int k = 0; k < cIN; k++) {
            a = fmaf(xs[k], inw[(size_t)k * cD + d], a);
        }
        size_t o = (size_t)bs * cD + d;
        g_h[o] = a;
        bf16 hi, lo;
        bsplit(a, hi, lo);
        g_hh[o] = hi;
        g_hl[o] = lo;
    }
}

// ---------------- softmax (row of 512), outputs P hi/lo ----------------
__global__ void __launch_bounds__(256) softmax_rows()
{
    size_t row = blockIdx.x;
    const float* p = g_s + row * cS;
    int tid = threadIdx.x;
    float v0 = p[tid];
    float v1 = p[tid + 256];
    __shared__ float sm[256];
    sm[tid] = fmaxf(v0, v1);
    __syncthreads();
    for (int s = 128; s > 0; s >>= 1) {
        if (tid < s) sm[tid] = fmaxf(sm[tid], sm[tid + s]);
        __syncthreads();
    }
    float m = sm[0];
    __syncthreads();
    float e0 = __expf(v0 - m);
    float e1 = __expf(v1 - m);
    sm[tid] = e0 + e1;
    __syncthreads();
    for (int s = 128; s > 0; s >>= 1) {
        if (tid < s) sm[tid] += sm[tid + s];
        __syncthreads();
    }
    float inv = 1.f / sm[0];
    bf16 hi, lo;
    bsplit(e0 * inv, hi, lo);
    g_ph[row * cS + tid] = hi;
    g_pl[row * cS + tid] = lo;
    bsplit(e1 * inv, hi, lo);
    g_ph[row * cS + tid + 256] = hi;
    g_pl[row * cS + tid + 256] = lo;
}

// ---------------- h = LayerNorm(h + add), writes fp32 + hi/lo ----------------
__global__ void __launch_bounds__(256) add_ln(
    const float* __restrict__ add, const float* __restrict__ gam,
    const float* __restrict__ bet)
{
    int row = blockIdx.x;
    int tid = threadIdx.x;
    __shared__ float sm[256];
    float v[3];
    float s = 0.f;
    #pragma unroll
    for (int i = 0; i < 3; i++) {
        int d = tid + i * 256;
        v[i] = g_h[(size_t)row * cD + d] + add[(size_t)row * cD + d];
        s += v[i];
    }
    sm[tid] = s;
    __syncthreads();
    for (int w = 128; w > 0; w >>= 1) {
        if (tid < w) sm[tid] += sm[tid + w];
        __syncthreads();
    }
    float mean = sm[0] * (1.f / 768.f);
    __syncthreads();
    float var = 0.f;
    #pragma unroll
    for (int i = 0; i < 3; i++) {
        float dv = v[i] - mean;
        var += dv * dv;
    }
    sm[tid] = var;
    __syncthreads();
    for (int w = 128; w > 0; w >>= 1) {
        if (tid < w) sm[tid] += sm[tid + w];
        __syncthreads();
    }
    float inv = rsqrtf(sm[0] * (1.f / 768.f) + cEPS);
    __syncthreads();
    #pragma unroll
    for (int i = 0; i < 3; i++) {
        int d = tid + i * 256;
        float r = (v[i] - mean) * inv * gam[d] + bet[d];
        size_t o = (size_t)row * cD + d;
        g_h[o] = r;
        bf16 hi, lo;
        bsplit(r, hi, lo);
        g_hh[o] = hi;
        g_hl[o] = lo;
    }
}

// ---------------- masked mean pool + out proj ----------------
__global__ void __launch_bounds__(256) pool_out(
    const int* __restrict__ lens, const float* __restrict__ ow,
    const float* __restrict__ ob, float* __restrict__ out)
{
    int b = blockIdx.x;
    int tid = threadIdx.x;
    int len = lens[b];
    float part = 0.f;
    for (int d = tid; d < cD; d += 256) {
        float s = 0.f;
        for (int t = 0; t < len; t++) {
            s += g_h[((size_t)(b * cS + t)) * cD + d];
        }
        part += (s / (float)len) * ow[d];
    }
    __shared__ float sm[256];
    sm[tid] = part;
    __syncthreads();
    for (int w = 128; w > 0; w >>= 1) {
        if (tid < w) sm[tid] += sm[tid + w];
        __syncthreads();
    }
    if (tid == 0) out[b] = sm[0] + ob[0];
}

// ---------------- launch ----------------
extern "C" void kernel_launch(void* const* d_in, const int* in_sizes, int n_in,
                              void* d_out, int out_size)
{
    const float* x    = (const float*)d_in[0];
    const int*   lens = (const int*)  d_in[1];
    const float* in_w = (const float*)d_in[2];
    const float* in_b = (const float*)d_in[3];
    const float* pos  = (const float*)d_in[4];
    const float* qw   = (const float*)d_in[5];
    const float* qb   = (const float*)d_in[6];
    const float* kw   = (const float*)d_in[7];
    const float* kb   = (const float*)d_in[8];
    const float* vw   = (const float*)d_in[9];
    const float* vb   = (const float*)d_in[10];
    const float* w1   = (const float*)d_in[11];
    const float* b1   = (const float*)d_in[12];
    const float* w2   = (const float*)d_in[13];
    const float* b2   = (const float*)d_in[14];
    const float* ln1g = (const float*)d_in[15];
    const float* ln1b = (const float*)d_in[16];
    const float* ln2g = (const float*)d_in[17];
    const float* ln2b = (const float*)d_in[18];
    const float* ow   = (const float*)d_in[19];
    const float* ob   = (const float*)d_in[20];
    float* out = (float*)d_out;

    void* sp = 0;
    cudaGetSymbolAddress(&sp, g_o);   float* po  = (float*)sp;
    cudaGetSymbolAddress(&sp, g_s);   float* ps  = (float*)sp;
    cudaGetSymbolAddress(&sp, g_hh);  bf16* phh  = (bf16*)sp;
    cudaGetSymbolAddress(&sp, g_hl);  bf16* phl  = (bf16*)sp;
    cudaGetSymbolAddress(&sp, g_qh);  bf16* pqh  = (bf16*)sp;
    cudaGetSymbolAddress(&sp, g_ql);  bf16* pql  = (bf16*)sp;
    cudaGetSymbolAddress(&sp, g_kh);  bf16* pkh  = (bf16*)sp;
    cudaGetSymbolAddress(&sp, g_kl);  bf16* pkl  = (bf16*)sp;
    cudaGetSymbolAddress(&sp, g_vth); bf16* pvth = (bf16*)sp;
    cudaGetSymbolAddress(&sp, g_vtl); bf16* pvtl = (bf16*)sp;
    cudaGetSymbolAddress(&sp, g_ph);  bf16* pph  = (bf16*)sp;
    cudaGetSymbolAddress(&sp, g_pl);  bf16* ppl  = (bf16*)sp;
    cudaGetSymbolAddress(&sp, g_fh);  bf16* pfh  = (bf16*)sp;
    cudaGetSymbolAddress(&sp, g_fl);  bf16* pfl  = (bf16*)sp;
    cudaGetSymbolAddress(&sp, g_wqh); bf16* wqh  = (bf16*)sp;
    cudaGetSymbolAddress(&sp, g_wql); bf16* wql  = (bf16*)sp;
    cudaGetSymbolAddress(&sp, g_wkh); bf16* wkh  = (bf16*)sp;
    cudaGetSymbolAddress(&sp, g_wkl); bf16* wkl  = (bf16*)sp;
    cudaGetSymbolAddress(&sp, g_wvh); bf16* wvh  = (bf16*)sp;
    cudaGetSymbolAddress(&sp, g_wvl); bf16* wvl  = (bf16*)sp;
    cudaGetSymbolAddress(&sp, g_w1h); bf16* w1h  = (bf16*)sp;
    cudaGetSymbolAddress(&sp, g_w1l); bf16* w1l  = (bf16*)sp;
    cudaGetSymbolAddress(&sp, g_w2h); bf16* w2h  = (bf16*)sp;
    cudaGetSymbolAddress(&sp, g_w2l); bf16* w2l  = (bf16*)sp;

    const int SM128 = 73728;   // tile smem (A hi/lo + B hi/lo, pitch-72); > sep 66048
    const int SM64  = 55296;
    cudaFuncSetAttribute(gemm_tc<128, 0>, cudaFuncAttributeMaxDynamicSharedMemorySize, SM128);
    cudaFuncSetAttribute(gemm_tc<128, 1>, cudaFuncAttributeMaxDynamicSharedMemorySize, SM128);
    cudaFuncSetAttribute(gemm_tc<128, 2>, cudaFuncAttributeMaxDynamicSharedMemorySize, SM128);
    cudaFuncSetAttribute(gemm_tc<128, 3>, cudaFuncAttributeMaxDynamicSharedMemorySize, SM128);
    cudaFuncSetAttribute(gemm_tc<128, 5>, cudaFuncAttributeMaxDynamicSharedMemorySize, SM128);
    cudaFuncSetAttribute(gemm_tc<64, 4>,  cudaFuncAttributeMaxDynamicSharedMemorySize, SM64);

    transpose_split<<<dim3(24, 24, cL), 256>>>(qw, wqh, wql, cD, cD);
    transpose_split<<<dim3(24, 24, cL), 256>>>(kw, wkh, wkl, cD, cD);
    transpose_split<<<dim3(24, 24, cL), 256>>>(vw, wvh, wvl, cD, cD);
    transpose_split<<<dim3(24, 96, cL), 256>>>(w1, w1h, w1l, cD, cF);
    transpose_split<<<dim3(96, 24, cL), 256>>>(w2, w2h, w2l, cF, cD);

    embed_kernel<<<cM, 256>>>(x, in_w, in_b, pos);

    for (int l = 0; l < cL; l++) {
        const size_t wo  = (size_t)l * cD * cD;
        const size_t w1o = (size_t)l * cD * cF;
        const size_t w2o = (size_t)l * cF * cD;

        gemm_tc<128, 1><<<dim3(6, 64, 1), 256, SM128>>>(
            phh, phl, wqh + wo, wql + wo, qb + l * cD, 0, pqh, pql,
            cD, cD, cD, cD, 0, 0, 0, 0, 0);
        gemm_tc<128, 1><<<dim3(6, 64, 1), 256, SM128>>>(
            phh, phl, wkh + wo, wkl + wo, kb + l * cD, 0, pkh, pkl,
            cD, cD, cD, cD, 0, 0, 0, 0, 0);
        gemm_tc<128, 2><<<dim3(6, 64, 1), 256, SM128>>>(
            phh, phl, wvh + wo, wvl + wo, vb + l * cD, 0, pvth, pvtl,
            cD, cD, cD, cD, 0, 0, 0, 0, 0);

        gemm_tc<128, 3><<<dim3(4, 4, cB * cH), 256, SM128>>>(
            pqh, pql, pkh, pkl, 0, ps, 0, 0,
            cDH, cD, cD, 0,
            (long long)cS * cD, (long long)cDH,
            (long long)cS * cD, (long long)cDH, lens);

        softmax_rows<<<cB * cH * cS, 256>>>();

        gemm_tc<64, 4><<<dim3(1, 4, cB * cH), 256, SM64>>>(
            pph, ppl, pvth, pvtl, 0, po, 0, 0,
            cS, cS, cS, 0,
            (long long)cH * cS * cS, (long long)cS * cS,
            (long long)cH * cDH * cS, (long long)cDH * cS, 0);

        add_ln<<<cM, 256>>>(po, ln1g + l * cD, ln1b + l * cD);

        gemm_tc<128, 5><<<dim3(24, 64, 1), 256, SM128>>>(
            phh, phl, w1h + w1o, w1l + w1o, b1 + l * cF, 0, pfh, pfl,
            cD, cD, cD, cF, 0, 0, 0, 0, 0);
        gemm_tc<128, 0><<<dim3(6, 64, 1), 256, SM128>>>(
            pfh, pfl, w2h + w2o, w2l + w2o, b2 + l * cD, po, 0, 0,
            cF, cF, cF, cD, 0, 0, 0, 0, 0);

        add_ln<<<cM, 256>>>(po, ln2g + l * cD, ln2b + l * cD);
    }

    pool_out<<<cB, 256>>>(lens, ow, ob, out);
}

// round 15
// speedup vs baseline: 1.1684x; 1.1684x over previous
#include <cuda_runtime.h>
#include <cuda_bf16.h>
#include <cstdint>

typedef __nv_bfloat16 bf16;

static constexpr int cB = 16;
static constexpr int cS = 512;
static constexpr int cIN = 32;
static constexpr int cD = 768;
static constexpr int cH = 12;
static constexpr int cDH = 64;
static constexpr int cL = 6;
static constexpr int cF = 3072;
static constexpr int cM = cB * cS;              // 8192 tokens
static constexpr float cEPS = 1e-5f;
static constexpr float cNEG = -1e9f;

// ---------------- scratch (device globals; no allocation) ----------------
__device__ __align__(256) float g_h[cM * cD];
__device__ __align__(256) float g_o[cM * cD];
__device__ __align__(256) float g_s[(size_t)cB * cH * cS * cS];
__device__ __align__(256) bf16 g_hh[cM * cD];
__device__ __align__(256) bf16 g_hl[cM * cD];
__device__ __align__(256) bf16 g_qh[cM * cD];
__device__ __align__(256) bf16 g_ql[cM * cD];
__device__ __align__(256) bf16 g_kh[cM * cD];
__device__ __align__(256) bf16 g_kl[cM * cD];
__device__ __align__(256) bf16 g_vth[cM * cD];
__device__ __align__(256) bf16 g_vtl[cM * cD];
__device__ __align__(256) bf16 g_ph[(size_t)cB * cH * cS * cS];
__device__ __align__(256) bf16 g_pl[(size_t)cB * cH * cS * cS];
__device__ __align__(256) bf16 g_fh[(size_t)cM * cF];
__device__ __align__(256) bf16 g_fl[(size_t)cM * cF];
__device__ __align__(256) bf16 g_wqh[cL * cD * cD];
__device__ __align__(256) bf16 g_wql[cL * cD * cD];
__device__ __align__(256) bf16 g_wkh[cL * cD * cD];
__device__ __align__(256) bf16 g_wkl[cL * cD * cD];
__device__ __align__(256) bf16 g_wvh[cL * cD * cD];
__device__ __align__(256) bf16 g_wvl[cL * cD * cD];
__device__ __align__(256) bf16 g_w1h[(size_t)cL * cD * cF];
__device__ __align__(256) bf16 g_w1l[(size_t)cL * cD * cF];
__device__ __align__(256) bf16 g_w2h[(size_t)cL * cF * cD];
__device__ __align__(256) bf16 g_w2l[(size_t)cL * cF * cD];

// ---------------- helpers ----------------
__device__ __forceinline__ uint32_t smem_to_u32(const void* smem_ptr) {
    uint32_t addr;
    asm("{ .reg .u64 tmp; cvta.to.shared.u64 tmp, %1; cvt.u32.u64 %0, tmp; }"
        : "=r"(addr) : "l"(smem_ptr));
    return addr;
}

#define LDSM_X4(r0, r1, r2, r3, addr) \
    asm volatile("ldmatrix.sync.aligned.m8n8.x4.shared.b16 {%0,%1,%2,%3}, [%4];" \
        : "=r"(r0), "=r"(r1), "=r"(r2), "=r"(r3) : "r"(addr))

#define MMA16816(d, a, b0, b1) \
    asm volatile("mma.sync.aligned.m16n8k16.row.col.f32.bf16.bf16.f32 " \
        "{%0,%1,%2,%3}, {%4,%5,%6,%7}, {%8,%9}, {%0,%1,%2,%3};" \
        : "+f"((d)[0]), "+f"((d)[1]), "+f"((d)[2]), "+f"((d)[3]) \
        : "r"((a)[0]), "r"((a)[1]), "r"((a)[2]), "r"((a)[3]), "r"(b0), "r"(b1))

#define CP_ASYNC16(dst, src) \
    asm volatile("cp.async.cg.shared.global [%0], [%1], 16;" \
        :: "r"(dst), "l"(src) : "memory")

#define CP_COMMIT() asm volatile("cp.async.commit_group;" ::: "memory")

template<int N>
__device__ __forceinline__ void cp_wait() {
    asm volatile("cp.async.wait_group %0;" :: "n"(N) : "memory");
}

__device__ __forceinline__ void bsplit(float v, bf16& hi, bf16& lo) {
    hi = __float2bfloat16(v);
    lo = __float2bfloat16(v - __bfloat162float(hi));
}

// ==========================================================================
// bf16x3 GEMM via mma.sync (HMMA), cp.async 2-stage pipeline.
// C[M,N] = A[M,K] @ B[N,K]^T.  M tile 128, N tile NT, K chunked by 32.
// 8 warps: warpM = wid&3 (32 rows), warpN = wid>>2 (NT/2 cols).
// Smem pitch 40 bf16 (80B rows): row starts tile all 32 banks; conflict-free.
// MODE: 0=fp32+bias  1=hi/lo+bias  2=V-transpose hi/lo+bias
//       3=scores (scale+mask, fp32)  4=PV (fp32 strided)  5=ReLU hi/lo+bias
// ==========================================================================
template<int NT, int MODE>
__global__ void __launch_bounds__(256, 2) gemm_tc(
    const bf16* __restrict__ Ah, const bf16* __restrict__ Al,
    const bf16* __restrict__ Bh, const bf16* __restrict__ Bl,
    const float* __restrict__ bias,
    float* __restrict__ outF, bf16* __restrict__ outH, bf16* __restrict__ outL,
    int K, int lda, int ldb, int ldOut,
    long long aS1, long long aS2, long long bS1, long long bS2,
    const int* __restrict__ lens)
{
    extern __shared__ char smem[];
    const uint32_t sb = smem_to_u32(smem);
    const int tid = threadIdx.x;
    const int wid = tid >> 5;
    const int lid = tid & 31;
    const int z = blockIdx.z;
    const int row0 = blockIdx.y * 128;
    const int col0 = blockIdx.x * NT;
    const size_t aOff = (size_t)(z / cH) * aS1 + (size_t)(z % cH) * aS2;
    const size_t bOff = (size_t)(z / cH) * bS1 + (size_t)(z % cH) * bS2;

    const int warpM = wid & 3;
    const int warpN = wid >> 2;
    constexpr int WN = NT / 2;
    constexpr int NTILES = NT / 16;

    constexpr uint32_t PITCH_E = 40;                      // 32 elems + 8 pad
    constexpr uint32_t ASZ = 128u * PITCH_E * 2u;         // 10240 per matrix
    constexpr uint32_t BSZ = (uint32_t)NT * PITCH_E * 2u;
    constexpr uint32_t STG = 2u * (ASZ + BSZ);            // stage bytes

    float acc[2][NTILES][4];
    #pragma unroll
    for (int mt = 0; mt < 2; mt++)
        #pragma unroll
        for (int nt = 0; nt < NTILES; nt++)
            #pragma unroll
            for (int i = 0; i < 4; i++)
                acc[mt][nt][i] = 0.f;

    auto issue_chunk = [&](int c, int s) {
        const uint32_t base = sb + (uint32_t)s * STG;
        const int k0c = c << 5;
        #pragma unroll
        for (int v = tid; v < 512; v += 256) {           // A: 128 x 32
            int r = v >> 2;
            int kc = (v & 3) << 3;
            size_t src = aOff + (size_t)(row0 + r) * lda + (size_t)(k0c + kc);
            uint32_t dst = base + (uint32_t)(r * PITCH_E + kc) * 2u;
            CP_ASYNC16(dst, Ah + src);
            CP_ASYNC16(dst + ASZ, Al + src);
        }
        #pragma unroll
        for (int v = tid; v < NT * 4; v += 256) {        // B: NT x 32
            int r = v >> 2;
            int kc = (v & 3) << 3;
            size_t src = bOff + (size_t)(col0 + r) * ldb + (size_t)(k0c + kc);
            uint32_t dst = base + 2u * ASZ + (uint32_t)(r * PITCH_E + kc) * 2u;
            CP_ASYNC16(dst, Bh + src);
            CP_ASYNC16(dst + BSZ, Bl + src);
        }
    };

    const int nch = K >> 5;
    issue_chunk(0, 0);
    CP_COMMIT();

    for (int c = 0; c < nch; c++) {
        if (c + 1 < nch) {
            issue_chunk(c + 1, (c + 1) & 1);
            CP_COMMIT();
            cp_wait<1>();
        } else {
            cp_wait<0>();
        }
        __syncthreads();

        const uint32_t base = sb + (uint32_t)(c & 1) * STG;
        #pragma unroll
        for (int p = 0; p < 3; p++) {    // hi*hi, hi*lo, lo*hi
            const uint32_t Ab = base + (p == 2 ? ASZ : 0u);
            const uint32_t Bb = base + 2u * ASZ + (p == 1 ? BSZ : 0u);
            #pragma unroll
            for (int ks = 0; ks < 2; ks++) {
                const int kk = ks * 16;
                uint32_t afr[2][4];
                #pragma unroll
                for (int mt = 0; mt < 2; mt++) {
                    uint32_t addr = Ab +
                        ((uint32_t)(warpM * 32 + mt * 16 + (lid & 15)) * PITCH_E
                         + (uint32_t)(kk + (lid >> 4) * 8)) * 2u;
                    LDSM_X4(afr[mt][0], afr[mt][1], afr[mt][2], afr[mt][3], addr);
                }
                #pragma unroll
                for (int nt = 0; nt < NTILES; nt += 2) {
                    uint32_t b0, b1, b2, b3;
                    uint32_t addr = Bb +
                        ((uint32_t)(warpN * WN + nt * 8 + ((lid >> 4) & 1) * 8 + (lid & 7)) * PITCH_E
                         + (uint32_t)(kk + ((lid >> 3) & 1) * 8)) * 2u;
                    LDSM_X4(b0, b1, b2, b3, addr);
                    #pragma unroll
                    for (int mt = 0; mt < 2; mt++) {
                        MMA16816(acc[mt][nt],     afr[mt], b0, b1);
                        MMA16816(acc[mt][nt + 1], afr[mt], b2, b3);
                    }
                }
            }
        }
        __syncthreads();
    }

    // --- epilogue 1: registers -> smem f32, pitch NT+1 ---
    const int PITCH = NT + 1;
    float* sep = (float*)smem;
    #pragma unroll
    for (int mt = 0; mt < 2; mt++)
        #pragma unroll
        for (int nt = 0; nt < NTILES; nt++)
            #pragma unroll
            for (int i = 0; i < 4; i++) {
                int row = warpM * 32 + mt * 16 + (lid >> 2) + (i >> 1) * 8;
                int col = warpN * WN + nt * 8 + (lid & 3) * 2 + (i & 1);
                sep[row * PITCH + col] = acc[mt][nt][i];
            }
    __syncthreads();

    // --- epilogue 2: smem -> global, per-mode ---
    const int total = 128 * NT;
    for (int i = tid; i < total; i += 256) {
        if (MODE == 2) {
            int r = i & 127;
            int c2 = i >> 7;
            float v = sep[r * PITCH + c2] + bias[col0 + c2];
            int tokr = row0 + r;
            int gb = tokr >> 9;
            int gs = tokr & (cS - 1);
            int gc = col0 + c2;
            int h2 = gc >> 6;
            int dd = gc & 63;
            size_t o = (((size_t)(gb * cH + h2)) * cDH + dd) * cS + gs;
            bf16 hi, lo;
            bsplit(v, hi, lo);
            outH[o] = hi;
            outL[o] = lo;
        } else if (MODE == 4) {
            int c2 = i & 63;
            int r = i >> 6;
            float v = sep[r * PITCH + c2];
            int gb = z / cH;
            int h2 = z % cH;
            outF[((size_t)gb * cS + row0 + r) * cD + h2 * cDH + c2] = v;
        } else if (MODE == 3) {
            int c2 = i & (NT - 1);
            int r = i / NT;
            float v = sep[r * PITCH + c2];
            int len = lens[z / cH];
            v = (row0 + r < len && col0 + c2 < len) ? v * 0.125f : cNEG;
            outF[((size_t)z * cS + row0 + r) * cS + col0 + c2] = v;
        } else {
            int c2 = i & (NT - 1);
            int r = i / NT;
            float v = sep[r * PITCH + c2] + bias[col0 + c2];
            if (MODE == 5) v = fmaxf(v, 0.f);
            size_t o = (size_t)(row0 + r) * ldOut + (size_t)(col0 + c2);
            if (MODE == 0) {
                outF[o] = v;
            } else {
                bf16 hi, lo;
                bsplit(v, hi, lo);
                outH[o] = hi;
                outL[o] = lo;
            }
        }
    }
}

// ---------------- weight transpose + split: W[K,N] -> WT[N,K] hi/lo ----------------
__global__ void __launch_bounds__(256) transpose_split(
    const float* __restrict__ src, bf16* __restrict__ dh, bf16* __restrict__ dl,
    int K, int N)
{
    __shared__ float t[32][33];
    size_t base = (size_t)blockIdx.z * K * N;
    int k0 = blockIdx.x * 32;
    int n0 = blockIdx.y * 32;
    int tx = threadIdx.x & 31;
    int ty = threadIdx.x >> 5;
    #pragma unroll
    for (int i = 0; i < 32; i += 8) {
        t[ty + i][tx] = src[base + (size_t)(k0 + ty + i) * N + (n0 + tx)];
    }
    __syncthreads();
    #pragma unroll
    for (int i = 0; i < 32; i += 8) {
        float v = t[tx][ty + i];
        size_t o = base + (size_t)(n0 + ty + i) * K + (k0 + tx);
        bf16 hi, lo;
        bsplit(v, hi, lo);
        dh[o] = hi;
        dl[o] = lo;
    }
}

// ---------------- embed ----------------
__global__ void __launch_bounds__(256) embed_kernel(
    const float* __restrict__ x, const float* __restrict__ inw,
    const float* __restrict__ inb, const float* __restrict__ pos)
{
    int bs = blockIdx.x;
    int s = bs & (cS - 1);
    __shared__ float xs[cIN];
    int tid = threadIdx.x;
    if (tid < cIN) xs[tid] = x[(size_t)bs * cIN + tid];
    __syncthreads();
    #pragma unroll
    for (int i = 0; i < 3; i++) {
        int d = tid + i * 256;
        float a = inb[d] + pos[(size_t)s * cD + d];
        #pragma unroll
        for (int k = 0; k < cIN; k++) {
            a = fmaf(xs[k], inw[(size_t)k * cD + d], a);
        }
        size_t o = (size_t)bs * cD + d;
        g_h[o] = a;
        bf16 hi, lo;
        bsplit(a, hi, lo);
        g_hh[o] = hi;
        g_hl[o] = lo;
    }
}

// ---------------- softmax (row of 512), outputs P hi/lo ----------------
__global__ void __launch_bounds__(256) softmax_rows()
{
    size_t row = blockIdx.x;
    const float* p = g_s + row * cS;
    int tid = threadIdx.x;
    float v0 = p[tid];
    float v1 = p[tid + 256];
    __shared__ float sm[256];
    sm[tid] = fmaxf(v0, v1);
    __syncthreads();
    for (int s = 128; s > 0; s >>= 1) {
        if (tid < s) sm[tid] = fmaxf(sm[tid], sm[tid + s]);
        __syncthreads();
    }
    float m = sm[0];
    __syncthreads();
    float e0 = __expf(v0 - m);
    float e1 = __expf(v1 - m);
    sm[tid] = e0 + e1;
    __syncthreads();
    for (int s = 128; s > 0; s >>= 1) {
        if (tid < s) sm[tid] += sm[tid + s];
        __syncthreads();
    }
    float inv = 1.f / sm[0];
    bf16 hi, lo;
    bsplit(e0 * inv, hi, lo);
    g_ph[row * cS + tid] = hi;
    g_pl[row * cS + tid] = lo;
    bsplit(e1 * inv, hi, lo);
    g_ph[row * cS + tid + 256] = hi;
    g_pl[row * cS + tid + 256] = lo;
}

// ---------------- h = LayerNorm(h + add), writes fp32 + hi/lo ----------------
__global__ void __launch_bounds__(256) add_ln(
    const float* __restrict__ add, const float* __restrict__ gam,
    const float* __restrict__ bet)
{
    int row = blockIdx.x;
    int tid = threadIdx.x;
    __shared__ float sm[256];
    float v[3];
    float s = 0.f;
    #pragma unroll
    for (int i = 0; i < 3; i++) {
        int d = tid + i * 256;
        v[i] = g_h[(size_t)row * cD + d] + add[(size_t)row * cD + d];
        s += v[i];
    }
    sm[tid] = s;
    __syncthreads();
    for (int w = 128; w > 0; w >>= 1) {
        if (tid < w) sm[tid] += sm[tid + w];
        __syncthreads();
    }
    float mean = sm[0] * (1.f / 768.f);
    __syncthreads();
    float var = 0.f;
    #pragma unroll
    for (int i = 0; i < 3; i++) {
        float dv = v[i] - mean;
        var += dv * dv;
    }
    sm[tid] = var;
    __syncthreads();
    for (int w = 128; w > 0; w >>= 1) {
        if (tid < w) sm[tid] += sm[tid + w];
        __syncthreads();
    }
    float inv = rsqrtf(sm[0] * (1.f / 768.f) + cEPS);
    __syncthreads();
    #pragma unroll
    for (int i = 0; i < 3; i++) {
        int d = tid + i * 256;
        float r = (v[i] - mean) * inv * gam[d] + bet[d];
        size_t o = (size_t)row * cD + d;
        g_h[o] = r;
        bf16 hi, lo;
        bsplit(r, hi, lo);
        g_hh[o] = hi;
        g_hl[o] = lo;
    }
}

// ---------------- masked mean pool + out proj ----------------
__global__ void __launch_bounds__(256) pool_out(
    const int* __restrict__ lens, const float* __restrict__ ow,
    const float* __restrict__ ob, float* __restrict__ out)
{
    int b = blockIdx.x;
    int tid = threadIdx.x;
    int len = lens[b];
    float part = 0.f;
    for (int d = tid; d < cD; d += 256) {
        float s = 0.f;
        for (int t = 0; t < len; t++) {
            s += g_h[((size_t)(b * cS + t)) * cD + d];
        }
        part += (s / (float)len) * ow[d];
    }
    __shared__ float sm[256];
    sm[tid] = part;
    __syncthreads();
    for (int w = 128; w > 0; w >>= 1) {
        if (tid < w) sm[tid] += sm[tid + w];
        __syncthreads();
    }
    if (tid == 0) out[b] = sm[0] + ob[0];
}

// ---------------- launch ----------------
extern "C" void kernel_launch(void* const* d_in, const int* in_sizes, int n_in,
                              void* d_out, int out_size)
{
    const float* x    = (const float*)d_in[0];
    const int*   lens = (const int*)  d_in[1];
    const float* in_w = (const float*)d_in[2];
    const float* in_b = (const float*)d_in[3];
    const float* pos  = (const float*)d_in[4];
    const float* qw   = (const float*)d_in[5];
    const float* qb   = (const float*)d_in[6];
    const float* kw   = (const float*)d_in[7];
    const float* kb   = (const float*)d_in[8];
    const float* vw   = (const float*)d_in[9];
    const float* vb   = (const float*)d_in[10];
    const float* w1   = (const float*)d_in[11];
    const float* b1   = (const float*)d_in[12];
    const float* w2   = (const float*)d_in[13];
    const float* b2   = (const float*)d_in[14];
    const float* ln1g = (const float*)d_in[15];
    const float* ln1b = (const float*)d_in[16];
    const float* ln2g = (const float*)d_in[17];
    const float* ln2b = (const float*)d_in[18];
    const float* ow   = (const float*)d_in[19];
    const float* ob   = (const float*)d_in[20];
    float* out = (float*)d_out;

    void* sp = 0;
    cudaGetSymbolAddress(&sp, g_o);   float* po  = (float*)sp;
    cudaGetSymbolAddress(&sp, g_s);   float* ps  = (float*)sp;
    cudaGetSymbolAddress(&sp, g_hh);  bf16* phh  = (bf16*)sp;
    cudaGetSymbolAddress(&sp, g_hl);  bf16* phl  = (bf16*)sp;
    cudaGetSymbolAddress(&sp, g_qh);  bf16* pqh  = (bf16*)sp;
    cudaGetSymbolAddress(&sp, g_ql);  bf16* pql  = (bf16*)sp;
    cudaGetSymbolAddress(&sp, g_kh);  bf16* pkh  = (bf16*)sp;
    cudaGetSymbolAddress(&sp, g_kl);  bf16* pkl  = (bf16*)sp;
    cudaGetSymbolAddress(&sp, g_vth); bf16* pvth = (bf16*)sp;
    cudaGetSymbolAddress(&sp, g_vtl); bf16* pvtl = (bf16*)sp;
    cudaGetSymbolAddress(&sp, g_ph);  bf16* pph  = (bf16*)sp;
    cudaGetSymbolAddress(&sp, g_pl);  bf16* ppl  = (bf16*)sp;
    cudaGetSymbolAddress(&sp, g_fh);  bf16* pfh  = (bf16*)sp;
    cudaGetSymbolAddress(&sp, g_fl);  bf16* pfl  = (bf16*)sp;
    cudaGetSymbolAddress(&sp, g_wqh); bf16* wqh  = (bf16*)sp;
    cudaGetSymbolAddress(&sp, g_wql); bf16* wql  = (bf16*)sp;
    cudaGetSymbolAddress(&sp, g_wkh); bf16* wkh  = (bf16*)sp;
    cudaGetSymbolAddress(&sp, g_wkl); bf16* wkl  = (bf16*)sp;
    cudaGetSymbolAddress(&sp, g_wvh); bf16* wvh  = (bf16*)sp;
    cudaGetSymbolAddress(&sp, g_wvl); bf16* wvl  = (bf16*)sp;
    cudaGetSymbolAddress(&sp, g_w1h); bf16* w1h  = (bf16*)sp;
    cudaGetSymbolAddress(&sp, g_w1l); bf16* w1l  = (bf16*)sp;
    cudaGetSymbolAddress(&sp, g_w2h); bf16* w2h  = (bf16*)sp;
    cudaGetSymbolAddress(&sp, g_w2l); bf16* w2l  = (bf16*)sp;

    const int SM128 = 81920;   // 2 stages x (A hi/lo + B hi/lo), pitch-40
    const int SM64  = 61440;
    cudaFuncSetAttribute(gemm_tc<128, 0>, cudaFuncAttributeMaxDynamicSharedMemorySize, SM128);
    cudaFuncSetAttribute(gemm_tc<128, 1>, cudaFuncAttributeMaxDynamicSharedMemorySize, SM128);
    cudaFuncSetAttribute(gemm_tc<128, 2>, cudaFuncAttributeMaxDynamicSharedMemorySize, SM128);
    cudaFuncSetAttribute(gemm_tc<128, 3>, cudaFuncAttributeMaxDynamicSharedMemorySize, SM128);
    cudaFuncSetAttribute(gemm_tc<128, 5>, cudaFuncAttributeMaxDynamicSharedMemorySize, SM128);
    cudaFuncSetAttribute(gemm_tc<64, 4>,  cudaFuncAttributeMaxDynamicSharedMemorySize, SM64);

    transpose_split<<<dim3(24, 24, cL), 256>>>(qw, wqh, wql, cD, cD);
    transpose_split<<<dim3(24, 24, cL), 256>>>(kw, wkh, wkl, cD, cD);
    transpose_split<<<dim3(24, 24, cL), 256>>>(vw, wvh, wvl, cD, cD);
    transpose_split<<<dim3(24, 96, cL), 256>>>(w1, w1h, w1l, cD, cF);
    transpose_split<<<dim3(96, 24, cL), 256>>>(w2, w2h, w2l, cF, cD);

    embed_kernel<<<cM, 256>>>(x, in_w, in_b, pos);

    for (int l = 0; l < cL; l++) {
        const size_t wo  = (size_t)l * cD * cD;
        const size_t w1o = (size_t)l * cD * cF;
        const size_t w2o = (size_t)l * cF * cD;

        gemm_tc<128, 1><<<dim3(6, 64, 1), 256, SM128>>>(
            phh, phl, wqh + wo, wql + wo, qb + l * cD, 0, pqh, pql,
            cD, cD, cD, cD, 0, 0, 0, 0, 0);
        gemm_tc<128, 1><<<dim3(6, 64, 1), 256, SM128>>>(
            phh, phl, wkh + wo, wkl + wo, kb + l * cD, 0, pkh, pkl,
            cD, cD, cD, cD, 0, 0, 0, 0, 0);
        gemm_tc<128, 2><<<dim3(6, 64, 1), 256, SM128>>>(
            phh, phl, wvh + wo, wvl + wo, vb + l * cD, 0, pvth, pvtl,
            cD, cD, cD, cD, 0, 0, 0, 0, 0);

        gemm_tc<128, 3><<<dim3(4, 4, cB * cH), 256, SM128>>>(
            pqh, pql, pkh, pkl, 0, ps, 0, 0,
            cDH, cD, cD, 0,
            (long long)cS * cD, (long long)cDH,
            (long long)cS * cD, (long long)cDH, lens);

        softmax_rows<<<cB * cH * cS, 256>>>();

        gemm_tc<64, 4><<<dim3(1, 4, cB * cH), 256, SM64>>>(
            pph, ppl, pvth, pvtl, 0, po, 0, 0,
            cS, cS, cS, 0,
            (long long)cH * cS * cS, (long long)cS * cS,
            (long long)cH * cDH * cS, (long long)cDH * cS, 0);

        add_ln<<<cM, 256>>>(po, ln1g + l * cD, ln1b + l * cD);

        gemm_tc<128, 5><<<dim3(24, 64, 1), 256, SM128>>>(
            phh, phl, w1h + w1o, w1l + w1o, b1 + l * cF, 0, pfh, pfl,
            cD, cD, cD, cF, 0, 0, 0, 0, 0);
        gemm_tc<128, 0><<<dim3(6, 64, 1), 256, SM128>>>(
            pfh, pfl, w2h + w2o, w2l + w2o, b2 + l * cD, po, 0, 0,
            cF, cF, cF, cD, 0, 0, 0, 0, 0);

        add_ln<<<cM, 256>>>(po, ln2g + l * cD, ln2b + l * cD);
    }

    pool_out<<<cB, 256>>>(lens, ow, ob, out);
}

// round 16
// speedup vs baseline: 2.3634x; 2.0227x over previous
#include <cuda_runtime.h>
#include <cuda_fp16.h>
#include <cstdint>

typedef __half fp16;

static constexpr int cB = 16;
static constexpr int cS = 512;
static constexpr int cIN = 32;
static constexpr int cD = 768;
static constexpr int cH = 12;
static constexpr int cDH = 64;
static constexpr int cL = 6;
static constexpr int cF = 3072;
static constexpr int cM = cB * cS;              // 8192 tokens
static constexpr float cEPS = 1e-5f;
static constexpr float cNEG = -1e9f;

// ---------------- scratch (device globals; no allocation) ----------------
__device__ __align__(256) float g_h[cM * cD];
__device__ __align__(256) float g_o[cM * cD];
__device__ __align__(256) float g_s[(size_t)cB * cH * cS * cS];
__device__ __align__(256) fp16 g_hh[cM * cD];
__device__ __align__(256) fp16 g_qh[cM * cD];
__device__ __align__(256) fp16 g_kh[cM * cD];
__device__ __align__(256) fp16 g_vth[cM * cD];          // [B,H,DH,S]
__device__ __align__(256) fp16 g_ph[(size_t)cB * cH * cS * cS];
__device__ __align__(256) fp16 g_fh[(size_t)cM * cF];
__device__ __align__(256) fp16 g_wq[cL * cD * cD];
__device__ __align__(256) fp16 g_wk[cL * cD * cD];
__device__ __align__(256) fp16 g_wv[cL * cD * cD];
__device__ __align__(256) fp16 g_w1[(size_t)cL * cD * cF];
__device__ __align__(256) fp16 g_w2[(size_t)cL * cF * cD];

// ---------------- helpers ----------------
__device__ __forceinline__ uint32_t smem_to_u32(const void* smem_ptr) {
    uint32_t addr;
    asm("{ .reg .u64 tmp; cvta.to.shared.u64 tmp, %1; cvt.u32.u64 %0, tmp; }"
        : "=r"(addr) : "l"(smem_ptr));
    return addr;
}

#define LDSM_X4(r0, r1, r2, r3, addr) \
    asm volatile("ldmatrix.sync.aligned.m8n8.x4.shared.b16 {%0,%1,%2,%3}, [%4];" \
        : "=r"(r0), "=r"(r1), "=r"(r2), "=r"(r3) : "r"(addr))

#define MMA16816(d, a, b0, b1) \
    asm volatile("mma.sync.aligned.m16n8k16.row.col.f32.f16.f16.f32 " \
        "{%0,%1,%2,%3}, {%4,%5,%6,%7}, {%8,%9}, {%0,%1,%2,%3};" \
        : "+f"((d)[0]), "+f"((d)[1]), "+f"((d)[2]), "+f"((d)[3]) \
        : "r"((a)[0]), "r"((a)[1]), "r"((a)[2]), "r"((a)[3]), "r"(b0), "r"(b1))

#define CP_ASYNC16(dst, src) \
    asm volatile("cp.async.cg.shared.global [%0], [%1], 16;" \
        :: "r"(dst), "l"(src) : "memory")

#define CP_COMMIT() asm volatile("cp.async.commit_group;" ::: "memory")

template<int N>
__device__ __forceinline__ void cp_wait() {
    asm volatile("cp.async.wait_group %0;" :: "n"(N) : "memory");
}

// ==========================================================================
// fp16 GEMM via mma.sync (HMMA), cp.async 2-stage pipeline.
// C[M,N] = A[M,K] @ B[N,K]^T.  M tile 128, N tile NT, K chunked by 64.
// 8 warps: warpM = wid&3 (32 rows), warpN = wid>>2 (NT/2 cols).
// Smem pitch 72 fp16 (144B rows): uint4-aligned, ldmatrix conflict-free.
// MODE: 0=fp32+bias  1=fp16+bias  2=V-transpose fp16+bias
//       3=scores (scale+mask, fp32)  4=PV (fp32 strided)  5=ReLU fp16+bias
// ==========================================================================
template<int NT, int MODE>
__global__ void __launch_bounds__(256, 2) gemm_tc(
    const fp16* __restrict__ A, const fp16* __restrict__ Bm,
    const float* __restrict__ bias,
    float* __restrict__ outF, fp16* __restrict__ outH,
    int K, int lda, int ldb, int ldOut,
    long long aS1, long long aS2, long long bS1, long long bS2,
    const int* __restrict__ lens)
{
    extern __shared__ char smem[];
    const uint32_t sb = smem_to_u32(smem);
    const int tid = threadIdx.x;
    const int wid = tid >> 5;
    const int lid = tid & 31;
    const int z = blockIdx.z;
    const int row0 = blockIdx.y * 128;
    const int col0 = blockIdx.x * NT;
    const size_t aOff = (size_t)(z / cH) * aS1 + (size_t)(z % cH) * aS2;
    const size_t bOff = (size_t)(z / cH) * bS1 + (size_t)(z % cH) * bS2;

    const int warpM = wid & 3;
    const int warpN = wid >> 2;
    constexpr int WN = NT / 2;
    constexpr int NTILES = NT / 16;

    constexpr uint32_t PITCH_E = 72;                      // 64 elems + 8 pad
    constexpr uint32_t ASZ = 128u * PITCH_E * 2u;         // 18432
    constexpr uint32_t BSZ = (uint32_t)NT * PITCH_E * 2u;
    constexpr uint32_t STG = ASZ + BSZ;                   // stage bytes

    float acc[2][NTILES][4];
    #pragma unroll
    for (int mt = 0; mt < 2; mt++)
        #pragma unroll
        for (int nt = 0; nt < NTILES; nt++)
            #pragma unroll
            for (int i = 0; i < 4; i++)
                acc[mt][nt][i] = 0.f;

    auto issue_chunk = [&](int c, int s) {
        const uint32_t base = sb + (uint32_t)s * STG;
        const int k0c = c << 6;
        #pragma unroll
        for (int v = tid; v < 1024; v += 256) {          // A: 128 x 64
            int r = v >> 3;
            int kc = (v & 7) << 3;
            size_t src = aOff + (size_t)(row0 + r) * lda + (size_t)(k0c + kc);
            uint32_t dst = base + (uint32_t)(r * PITCH_E + kc) * 2u;
            CP_ASYNC16(dst, A + src);
        }
        #pragma unroll
        for (int v = tid; v < NT * 8; v += 256) {        // B: NT x 64
            int r = v >> 3;
            int kc = (v & 7) << 3;
            size_t src = bOff + (size_t)(col0 + r) * ldb + (size_t)(k0c + kc);
            uint32_t dst = base + ASZ + (uint32_t)(r * PITCH_E + kc) * 2u;
            CP_ASYNC16(dst, Bm + src);
        }
    };

    const int nch = K >> 6;
    issue_chunk(0, 0);
    CP_COMMIT();

    for (int c = 0; c < nch; c++) {
        if (c + 1 < nch) {
            issue_chunk(c + 1, (c + 1) & 1);
            CP_COMMIT();
            cp_wait<1>();
        } else {
            cp_wait<0>();
        }
        __syncthreads();

        const uint32_t base = sb + (uint32_t)(c & 1) * STG;
        const uint32_t Ab = base;
        const uint32_t Bb = base + ASZ;
        #pragma unroll
        for (int ks = 0; ks < 4; ks++) {
            const int kk = ks * 16;
            uint32_t afr[2][4];
            #pragma unroll
            for (int mt = 0; mt < 2; mt++) {
                uint32_t addr = Ab +
                    ((uint32_t)(warpM * 32 + mt * 16 + (lid & 15)) * PITCH_E
                     + (uint32_t)(kk + (lid >> 4) * 8)) * 2u;
                LDSM_X4(afr[mt][0], afr[mt][1], afr[mt][2], afr[mt][3], addr);
            }
            #pragma unroll
            for (int nt = 0; nt < NTILES; nt += 2) {
                uint32_t b0, b1, b2, b3;
                uint32_t addr = Bb +
                    ((uint32_t)(warpN * WN + nt * 8 + ((lid >> 4) & 1) * 8 + (lid & 7)) * PITCH_E
                     + (uint32_t)(kk + ((lid >> 3) & 1) * 8)) * 2u;
                LDSM_X4(b0, b1, b2, b3, addr);
                #pragma unroll
                for (int mt = 0; mt < 2; mt++) {
                    MMA16816(acc[mt][nt],     afr[mt], b0, b1);
                    MMA16816(acc[mt][nt + 1], afr[mt], b2, b3);
                }
            }
        }
        __syncthreads();
    }

    // --- epilogue 1: registers -> smem f32, pitch NT+1 ---
    const int PITCH = NT + 1;
    float* sep = (float*)smem;
    #pragma unroll
    for (int mt = 0; mt < 2; mt++)
        #pragma unroll
        for (int nt = 0; nt < NTILES; nt++)
            #pragma unroll
            for (int i = 0; i < 4; i++) {
                int row = warpM * 32 + mt * 16 + (lid >> 2) + (i >> 1) * 8;
                int col = warpN * WN + nt * 8 + (lid & 3) * 2 + (i & 1);
                sep[row * PITCH + col] = acc[mt][nt][i];
            }
    __syncthreads();

    // --- epilogue 2: smem -> global, per-mode ---
    const int total = 128 * NT;
    for (int i = tid; i < total; i += 256) {
        if (MODE == 2) {
            int r = i & 127;
            int c2 = i >> 7;
            float v = sep[r * PITCH + c2] + bias[col0 + c2];
            int tokr = row0 + r;
            int gb = tokr >> 9;
            int gs = tokr & (cS - 1);
            int gc = col0 + c2;
            int h2 = gc >> 6;
            int dd = gc & 63;
            size_t o = (((size_t)(gb * cH + h2)) * cDH + dd) * cS + gs;
            outH[o] = __float2half(v);
        } else if (MODE == 4) {
            int c2 = i & 63;
            int r = i >> 6;
            float v = sep[r * PITCH + c2];
            int gb = z / cH;
            int h2 = z % cH;
            outF[((size_t)gb * cS + row0 + r) * cD + h2 * cDH + c2] = v;
        } else if (MODE == 3) {
            int c2 = i & (NT - 1);
            int r = i / NT;
            float v = sep[r * PITCH + c2];
            int len = lens[z / cH];
            v = (row0 + r < len && col0 + c2 < len) ? v * 0.125f : cNEG;
            outF[((size_t)z * cS + row0 + r) * cS + col0 + c2] = v;
        } else {
            int c2 = i & (NT - 1);
            int r = i / NT;
            float v = sep[r * PITCH + c2] + bias[col0 + c2];
            if (MODE == 5) v = fmaxf(v, 0.f);
            size_t o = (size_t)(row0 + r) * ldOut + (size_t)(col0 + c2);
            if (MODE == 0) {
                outF[o] = v;
            } else {
                outH[o] = __float2half(v);
            }
        }
    }
}

// ---------------- weight transpose: W[K,N] -> WT[N,K] fp16 ----------------
__global__ void __launch_bounds__(256) transpose_split(
    const float* __restrict__ src, fp16* __restrict__ dh,
    int K, int N)
{
    __shared__ float t[32][33];
    size_t base = (size_t)blockIdx.z * K * N;
    int k0 = blockIdx.x * 32;
    int n0 = blockIdx.y * 32;
    int tx = threadIdx.x & 31;
    int ty = threadIdx.x >> 5;
    #pragma unroll
    for (int i = 0; i < 32; i += 8) {
        t[ty + i][tx] = src[base + (size_t)(k0 + ty + i) * N + (n0 + tx)];
    }
    __syncthreads();
    #pragma unroll
    for (int i = 0; i < 32; i += 8) {
        float v = t[tx][ty + i];
        size_t o = base + (size_t)(n0 + ty + i) * K + (k0 + tx);
        dh[o] = __float2half(v);
    }
}

// ---------------- embed ----------------
__global__ void __launch_bounds__(256) embed_kernel(
    const float* __restrict__ x, const float* __restrict__ inw,
    const float* __restrict__ inb, const float* __restrict__ pos)
{
    int bs = blockIdx.x;
    int s = bs & (cS - 1);
    __shared__ float xs[cIN];
    int tid = threadIdx.x;
    if (tid < cIN) xs[tid] = x[(size_t)bs * cIN + tid];
    __syncthreads();
    #pragma unroll
    for (int i = 0; i < 3; i++) {
        int d = tid + i * 256;
        float a = inb[d] + pos[(size_t)s * cD + d];
        #pragma unroll
        for (int k = 0; k < cIN; k++) {
            a = fmaf(xs[k], inw[(size_t)k * cD + d], a);
        }
        size_t o = (size_t)bs * cD + d;
        g_h[o] = a;
        g_hh[o] = __float2half(a);
    }
}

// ---------------- softmax (row of 512), outputs P fp16 ----------------
__global__ void __launch_bounds__(256) softmax_rows()
{
    size_t row = blockIdx.x;
    const float* p = g_s + row * cS;
    int tid = threadIdx.x;
    float v0 = p[tid];
    float v1 = p[tid + 256];
    __shared__ float sm[256];
    sm[tid] = fmaxf(v0, v1);
    __syncthreads();
    for (int s = 128; s > 0; s >>= 1) {
        if (tid < s) sm[tid] = fmaxf(sm[tid], sm[tid + s]);
        __syncthreads();
    }
    float m = sm[0];
    __syncthreads();
    float e0 = __expf(v0 - m);
    float e1 = __expf(v1 - m);
    sm[tid] = e0 + e1;
    __syncthreads();
    for (int s = 128; s > 0; s >>= 1) {
        if (tid < s) sm[tid] += sm[tid + s];
        __syncthreads();
    }
    float inv = 1.f / sm[0];
    g_ph[row * cS + tid] = __float2half(e0 * inv);
    g_ph[row * cS + tid + 256] = __float2half(e1 * inv);
}

// ---------------- h = LayerNorm(h + add), writes fp32 + fp16 ----------------
__global__ void __launch_bounds__(256) add_ln(
    const float* __restrict__ add, const float* __restrict__ gam,
    const float* __restrict__ bet)
{
    int row = blockIdx.x;
    int tid = threadIdx.x;
    __shared__ float sm[256];
    float v[3];
    float s = 0.f;
    #pragma unroll
    for (int i = 0; i < 3; i++) {
        int d = tid + i * 256;
        v[i] = g_h[(size_t)row * cD + d] + add[(size_t)row * cD + d];
        s += v[i];
    }
    sm[tid] = s;
    __syncthreads();
    for (int w = 128; w > 0; w >>= 1) {
        if (tid < w) sm[tid] += sm[tid + w];
        __syncthreads();
    }
    float mean = sm[0] * (1.f / 768.f);
    __syncthreads();
    float var = 0.f;
    #pragma unroll
    for (int i = 0; i < 3; i++) {
        float dv = v[i] - mean;
        var += dv * dv;
    }
    sm[tid] = var;
    __syncthreads();
    for (int w = 128; w > 0; w >>= 1) {
        if (tid < w) sm[tid] += sm[tid + w];
        __syncthreads();
    }
    float inv = rsqrtf(sm[0] * (1.f / 768.f) + cEPS);
    __syncthreads();
    #pragma unroll
    for (int i = 0; i < 3; i++) {
        int d = tid + i * 256;
        float r = (v[i] - mean) * inv * gam[d] + bet[d];
        size_t o = (size_t)row * cD + d;
        g_h[o] = r;
        g_hh[o] = __float2half(r);
    }
}

// ---------------- masked mean pool + out proj ----------------
__global__ void __launch_bounds__(256) pool_out(
    const int* __restrict__ lens, const float* __restrict__ ow,
    const float* __restrict__ ob, float* __restrict__ out)
{
    int b = blockIdx.x;
    int tid = threadIdx.x;
    int len = lens[b];
    float part = 0.f;
    for (int d = tid; d < cD; d += 256) {
        float s = 0.f;
        for (int t = 0; t < len; t++) {
            s += g_h[((size_t)(b * cS + t)) * cD + d];
        }
        part += (s / (float)len) * ow[d];
    }
    __shared__ float sm[256];
    sm[tid] = part;
    __syncthreads();
    for (int w = 128; w > 0; w >>= 1) {
        if (tid < w) sm[tid] += sm[tid + w];
        __syncthreads();
    }
    if (tid == 0) out[b] = sm[0] + ob[0];
}

// ---------------- launch ----------------
extern "C" void kernel_launch(void* const* d_in, const int* in_sizes, int n_in,
                              void* d_out, int out_size)
{
    const float* x    = (const float*)d_in[0];
    const int*   lens = (const int*)  d_in[1];
    const float* in_w = (const float*)d_in[2];
    const float* in_b = (const float*)d_in[3];
    const float* pos  = (const float*)d_in[4];
    const float* qw   = (const float*)d_in[5];
    const float* qb   = (const float*)d_in[6];
    const float* kw   = (const float*)d_in[7];
    const float* kb   = (const float*)d_in[8];
    const float* vw   = (const float*)d_in[9];
    const float* vb   = (const float*)d_in[10];
    const float* w1   = (const float*)d_in[11];
    const float* b1   = (const float*)d_in[12];
    const float* w2   = (const float*)d_in[13];
    const float* b2   = (const float*)d_in[14];
    const float* ln1g = (const float*)d_in[15];
    const float* ln1b = (const float*)d_in[16];
    const float* ln2g = (const float*)d_in[17];
    const float* ln2b = (const float*)d_in[18];
    const float* ow   = (const float*)d_in[19];
    const float* ob   = (const float*)d_in[20];
    float* out = (float*)d_out;

    void* sp = 0;
    cudaGetSymbolAddress(&sp, g_o);   float* po  = (float*)sp;
    cudaGetSymbolAddress(&sp, g_s);   float* ps  = (float*)sp;
    cudaGetSymbolAddress(&sp, g_hh);  fp16* phh  = (fp16*)sp;
    cudaGetSymbolAddress(&sp, g_qh);  fp16* pqh  = (fp16*)sp;
    cudaGetSymbolAddress(&sp, g_kh);  fp16* pkh  = (fp16*)sp;
    cudaGetSymbolAddress(&sp, g_vth); fp16* pvth = (fp16*)sp;
    cudaGetSymbolAddress(&sp, g_ph);  fp16* pph  = (fp16*)sp;
    cudaGetSymbolAddress(&sp, g_fh);  fp16* pfh  = (fp16*)sp;
    cudaGetSymbolAddress(&sp, g_wq);  fp16* wq   = (fp16*)sp;
    cudaGetSymbolAddress(&sp, g_wk);  fp16* wk   = (fp16*)sp;
    cudaGetSymbolAddress(&sp, g_wv);  fp16* wv   = (fp16*)sp;
    cudaGetSymbolAddress(&sp, g_w1);  fp16* w1p  = (fp16*)sp;
    cudaGetSymbolAddress(&sp, g_w2);  fp16* w2p  = (fp16*)sp;

    const int SM128 = 73728;   // 2 stages x (A + B), pitch-72; > sep 66048
    const int SM64  = 55296;
    cudaFuncSetAttribute(gemm_tc<128, 0>, cudaFuncAttributeMaxDynamicSharedMemorySize, SM128);
    cudaFuncSetAttribute(gemm_tc<128, 1>, cudaFuncAttributeMaxDynamicSharedMemorySize, SM128);
    cudaFuncSetAttribute(gemm_tc<128, 2>, cudaFuncAttributeMaxDynamicSharedMemorySize, SM128);
    cudaFuncSetAttribute(gemm_tc<128, 3>, cudaFuncAttributeMaxDynamicSharedMemorySize, SM128);
    cudaFuncSetAttribute(gemm_tc<128, 5>, cudaFuncAttributeMaxDynamicSharedMemorySize, SM128);
    cudaFuncSetAttribute(gemm_tc<64, 4>,  cudaFuncAttributeMaxDynamicSharedMemorySize, SM64);

    transpose_split<<<dim3(24, 24, cL), 256>>>(qw, wq, cD, cD);
    transpose_split<<<dim3(24, 24, cL), 256>>>(kw, wk, cD, cD);
    transpose_split<<<dim3(24, 24, cL), 256>>>(vw, wv, cD, cD);
    transpose_split<<<dim3(24, 96, cL), 256>>>(w1, w1p, cD, cF);
    transpose_split<<<dim3(96, 24, cL), 256>>>(w2, w2p, cF, cD);

    embed_kernel<<<cM, 256>>>(x, in_w, in_b, pos);

    for (int l = 0; l < cL; l++) {
        const size_t wo  = (size_t)l * cD * cD;
        const size_t w1o = (size_t)l * cD * cF;
        const size_t w2o = (size_t)l * cF * cD;

        gemm_tc<128, 1><<<dim3(6, 64, 1), 256, SM128>>>(
            phh, wq + wo, qb + l * cD, 0, pqh,
            cD, cD, cD, cD, 0, 0, 0, 0, 0);
        gemm_tc<128, 1><<<dim3(6, 64, 1), 256, SM128>>>(
            phh, wk + wo, kb + l * cD, 0, pkh,
            cD, cD, cD, cD, 0, 0, 0, 0, 0);
        gemm_tc<128, 2><<<dim3(6, 64, 1), 256, SM128>>>(
            phh, wv + wo, vb + l * cD, 0, pvth,
            cD, cD, cD, cD, 0, 0, 0, 0, 0);

        gemm_tc<128, 3><<<dim3(4, 4, cB * cH), 256, SM128>>>(
            pqh, pkh, 0, ps, 0,
            cDH, cD, cD, 0,
            (long long)cS * cD, (long long)cDH,
            (long long)cS * cD, (long long)cDH, lens);

        softmax_rows<<<cB * cH * cS, 256>>>();

        gemm_tc<64, 4><<<dim3(1, 4, cB * cH), 256, SM64>>>(
            pph, pvth, 0, po, 0,
            cS, cS, cS, 0,
            (long long)cH * cS * cS, (long long)cS * cS,
            (long long)cH * cDH * cS, (long long)cDH * cS, 0);

        add_ln<<<cM, 256>>>(po, ln1g + l * cD, ln1b + l * cD);

        gemm_tc<128, 5><<<dim3(24, 64, 1), 256, SM128>>>(
            phh, w1p + w1o, b1 + l * cF, 0, pfh,
            cD, cD, cD, cF, 0, 0, 0, 0, 0);
        gemm_tc<128, 0><<<dim3(6, 64, 1), 256, SM128>>>(
            pfh, w2p + w2o, b2 + l * cD, po, 0,
            cF, cF, cF, cD, 0, 0, 0, 0, 0);

        add_ln<<<cM, 256>>>(po, ln2g + l * cD, ln2b + l * cD);
    }

    pool_out<<<cB, 256>>>(lens, ow, ob, out);
}